// round 6
// baseline (speedup 1.0000x reference)
#include <cuda_runtime.h>
#include <math.h>
#include <stdint.h>

// Problem constants
#define B_   8
#define S_   8192
#define D_   1024
#define H_   16
#define GS_  16
#define K_   64
#define HD_  64
#define G_   512            // S/GS groups per batch
#define F_   256            // DH4 scorer hidden
#define BG_  (B_*G_)        // 4096
#define BK_  (B_*K_)        // 512

// ---------------- scratch (static __device__, no allocation) ----------------
__device__ float g_groups[BG_*D_];
__device__ float g_h[BG_*F_];
__device__ float g_scores[BG_];
__device__ int   g_topidx[BK_];
__device__ int   g_selmap[BG_];
__device__ float g_q[BK_*D_];
__device__ float g_k[BK_*D_];
__device__ float g_v[BK_*D_];
__device__ float g_ctx[BK_*D_];
__device__ float g_outg[BK_*D_];

// ---------------- 1. group mean pool ----------------
__global__ void pool_kernel(const float* __restrict__ hs) {
    int bg = blockIdx.x;
    int b = bg >> 9, g = bg & 511;
    const float* base = hs + (b*S_ + g*GS_) * D_;
    int d4 = threadIdx.x * 4;
    float4 acc = make_float4(0.f, 0.f, 0.f, 0.f);
#pragma unroll
    for (int r = 0; r < GS_; r++) {
        float4 v = *(const float4*)(base + r*D_ + d4);
        acc.x += v.x; acc.y += v.y; acc.z += v.z; acc.w += v.w;
    }
    const float inv = 1.0f / (float)GS_;
    acc.x *= inv; acc.y *= inv; acc.z *= inv; acc.w *= inv;
    *(float4*)(g_groups + bg*D_ + d4) = acc;
}

// ---------------- tf32 helpers ----------------
__device__ __forceinline__ void split_tf32(float x, float& hi, float& lo) {
    uint32_t h;
    asm("cvt.rna.tf32.f32 %0, %1;" : "=r"(h) : "f"(x));
    hi = __uint_as_float(h);
    float r = x - hi;
    uint32_t l;
    asm("cvt.rna.tf32.f32 %0, %1;" : "=r"(l) : "f"(r));
    lo = __uint_as_float(l);
}

__device__ __forceinline__ void mma_tf32(float acc[4], const float a[4], const float b[2]) {
    uint32_t a0 = __float_as_uint(a[0]), a1 = __float_as_uint(a[1]);
    uint32_t a2 = __float_as_uint(a[2]), a3 = __float_as_uint(a[3]);
    uint32_t b0 = __float_as_uint(b[0]), b1 = __float_as_uint(b[1]);
    asm volatile(
        "mma.sync.aligned.m16n8k8.row.col.f32.tf32.tf32.f32 "
        "{%0,%1,%2,%3}, {%4,%5,%6,%7}, {%8,%9}, {%0,%1,%2,%3};\n"
        : "+f"(acc[0]), "+f"(acc[1]), "+f"(acc[2]), "+f"(acc[3])
        : "r"(a0), "r"(a1), "r"(a2), "r"(a3), "r"(b0), "r"(b1));
}

// ---------------- tensor-core GEMM: C = A[M,K] @ B[K,N], 3xTF32 ----------------
// 128 threads (4 warps, 2x2), block tile 64x64, K-chunk 32, warp tile 32x32.
// Pre-split hi/lo tf32 planes in smem, [k][m]/[k][n] layout stride 72 ->
// conflict-free fragment LDS, no cvt in inner loop.
// USE_ROWMAP: A row r reads g_groups[(r>>6)*G_ + g_topidx[r]] (fused gather).
#define KC_ 32
#define ST_ 72

template<bool USE_ROWMAP>
__global__ void gemm_tf32_3x(const float* __restrict__ A,
                             const float* __restrict__ B0,
                             const float* __restrict__ B1,
                             const float* __restrict__ B2,
                             float* __restrict__ C0,
                             float* __restrict__ C1,
                             float* __restrict__ C2,
                             int M, int N, int Kd) {
    const float* Bm = (blockIdx.z == 0) ? B0 : ((blockIdx.z == 1) ? B1 : B2);
    float* C       = (blockIdx.z == 0) ? C0 : ((blockIdx.z == 1) ? C1 : C2);

    __shared__ float Ah[KC_][ST_], Al[KC_][ST_];   // [k][m]
    __shared__ float Bh[KC_][ST_], Bl[KC_][ST_];   // [k][n]

    int tid = threadIdx.x;
    int lane = tid & 31, wid = tid >> 5;
    int wm = wid & 1, wn = wid >> 1;
    int g = lane >> 2, tig = lane & 3;

    int m0 = blockIdx.y * 64, n0 = blockIdx.x * 64;

    // A: thread loads 4 float4 along k from one row
    int arow = tid >> 1;                 // 0..63
    int acol0 = (tid & 1) << 2;          // 0 / 4, +8*i
    int agrow = m0 + arow;
    if (USE_ROWMAP) agrow = ((agrow >> 6) << 9) + g_topidx[agrow];
    const float* Arow = A + (size_t)agrow * Kd;

    // B: thread loads 4 float4 along n
    int brow0 = tid >> 4;                // 0..7, +8*i
    int bcol = (tid & 15) << 2;          // 0..60
    const float* Bbase = Bm + (size_t)brow0 * N + n0 + bcol;

    float acc[2][4][4];
#pragma unroll
    for (int sm = 0; sm < 2; sm++)
#pragma unroll
        for (int sn = 0; sn < 4; sn++)
#pragma unroll
            for (int i = 0; i < 4; i++) acc[sm][sn][i] = 0.f;

    for (int k0 = 0; k0 < Kd; k0 += KC_) {
        // ---- load + split A tile -> transposed planes ----
#pragma unroll
        for (int i = 0; i < 4; i++) {
            int c = acol0 + i*8;
            float4 v = *(const float4*)(Arow + k0 + c);
            float h0,l0,h1,l1,h2,l2,h3,l3;
            split_tf32(v.x, h0, l0); split_tf32(v.y, h1, l1);
            split_tf32(v.z, h2, l2); split_tf32(v.w, h3, l3);
            Ah[c+0][arow] = h0; Al[c+0][arow] = l0;
            Ah[c+1][arow] = h1; Al[c+1][arow] = l1;
            Ah[c+2][arow] = h2; Al[c+2][arow] = l2;
            Ah[c+3][arow] = h3; Al[c+3][arow] = l3;
        }
        // ---- load + split B tile ----
#pragma unroll
        for (int i = 0; i < 4; i++) {
            int r = brow0 + i*8;
            float4 v = *(const float4*)(Bbase + (size_t)(k0 + i*8) * N);
            float4 h, l;
            split_tf32(v.x, h.x, l.x); split_tf32(v.y, h.y, l.y);
            split_tf32(v.z, h.z, l.z); split_tf32(v.w, h.w, l.w);
            *(float4*)(&Bh[r][bcol]) = h;
            *(float4*)(&Bl[r][bcol]) = l;
        }
        __syncthreads();

#pragma unroll
        for (int k8 = 0; k8 < KC_; k8 += 8) {
            int ka = k8 + tig;
            float ahf[2][4], alf[2][4];
#pragma unroll
            for (int sm = 0; sm < 2; sm++) {
                int mb = wm*32 + sm*16;
                ahf[sm][0] = Ah[ka  ][mb + g    ];  alf[sm][0] = Al[ka  ][mb + g    ];
                ahf[sm][1] = Ah[ka  ][mb + g + 8];  alf[sm][1] = Al[ka  ][mb + g + 8];
                ahf[sm][2] = Ah[ka+4][mb + g    ];  alf[sm][2] = Al[ka+4][mb + g    ];
                ahf[sm][3] = Ah[ka+4][mb + g + 8];  alf[sm][3] = Al[ka+4][mb + g + 8];
            }
            float bhf[4][2], blf[4][2];
#pragma unroll
            for (int sn = 0; sn < 4; sn++) {
                int nb = wn*32 + sn*8 + g;
                bhf[sn][0] = Bh[ka  ][nb];  blf[sn][0] = Bl[ka  ][nb];
                bhf[sn][1] = Bh[ka+4][nb];  blf[sn][1] = Bl[ka+4][nb];
            }
#pragma unroll
            for (int sm = 0; sm < 2; sm++)
#pragma unroll
                for (int sn = 0; sn < 4; sn++) {
                    mma_tf32(acc[sm][sn], alf[sm], bhf[sn]);
                    mma_tf32(acc[sm][sn], ahf[sm], blf[sn]);
                    mma_tf32(acc[sm][sn], ahf[sm], bhf[sn]);
                }
        }
        __syncthreads();
    }

#pragma unroll
    for (int sm = 0; sm < 2; sm++)
#pragma unroll
        for (int sn = 0; sn < 4; sn++) {
            int row = m0 + wm*32 + sm*16 + g;
            int col = n0 + wn*32 + sn*8 + tig*2;
            *(float2*)(C + (size_t)row*N + col)     = make_float2(acc[sm][sn][0], acc[sm][sn][1]);
            *(float2*)(C + (size_t)(row+8)*N + col) = make_float2(acc[sm][sn][2], acc[sm][sn][3]);
        }
}

// ---------------- 2b. scorer epilogue: bias -> relu -> dot Ws2 ----------------
__global__ void score_reduce(const float* __restrict__ bs1,
                             const float* __restrict__ Ws2,
                             const float* __restrict__ bs2) {
    int g = blockIdx.x * 8 + (threadIdx.x >> 5);
    int lane = threadIdx.x & 31;
    float s = 0.f;
#pragma unroll
    for (int i = 0; i < 8; i++) {
        int f = lane + i*32;
        float v = g_h[g*F_ + f] + bs1[f];
        s += fmaxf(v, 0.f) * Ws2[f];
    }
#pragma unroll
    for (int o = 16; o; o >>= 1) s += __shfl_xor_sync(0xffffffffu, s, o);
    if (lane == 0) g_scores[g] = s + bs2[0];
}

// ---------------- 3. top-64 via bitonic sort (desc by score, asc by idx) -----
__global__ void topk_bitonic() {
    int b = blockIdx.x;
    int t = threadIdx.x;    // 512
    __shared__ float sv[512];
    __shared__ int   si[512];
    sv[t] = g_scores[b*G_ + t];
    si[t] = t;
    __syncthreads();
    for (int k = 2; k <= 512; k <<= 1) {
        for (int j = k >> 1; j > 0; j >>= 1) {
            int ixj = t ^ j;
            if (ixj > t) {
                float v1 = sv[t], v2 = sv[ixj];
                int   i1 = si[t], i2 = si[ixj];
                bool lt12 = (v1 < v2) || (v1 == v2 && i1 > i2);
                bool swap = ((t & k) == 0) ? lt12 : !lt12;
                if (swap) { sv[t] = v2; sv[ixj] = v1; si[t] = i2; si[ixj] = i1; }
            }
            __syncthreads();
        }
    }
    int gi = si[t];
    if (t < K_) {
        g_topidx[b*K_ + t] = gi;
        g_selmap[b*G_ + gi] = t;
    } else {
        g_selmap[b*G_ + gi] = -1;
    }
}

// ---------------- 6. attention per (b, head): 64x64, HD=64 ----------------
__global__ void attn_kernel() {
    int bh = blockIdx.x;
    int b = bh >> 4, h = bh & 15;
    __shared__ float Qs[64][65];
    __shared__ float KV[64][64];
    int t = threadIdx.x;
    const float* qbase = g_q + (b*K_)*D_ + h*HD_;
    const float* kbase = g_k + (b*K_)*D_ + h*HD_;
    const float* vbase = g_v + (b*K_)*D_ + h*HD_;
    for (int i = 0; i < 64; i++) {
        Qs[i][t] = qbase[i*D_ + t];
        KV[i][t] = kbase[i*D_ + t];
    }
    __syncthreads();
    float s[64];
#pragma unroll
    for (int j = 0; j < 64; j++) s[j] = 0.f;
    for (int d = 0; d < 64; d++) {
        float qd = Qs[t][d];
#pragma unroll
        for (int j = 0; j < 64; j++) s[j] += qd * KV[j][d];
    }
    float m = -INFINITY;
#pragma unroll
    for (int j = 0; j < 64; j++) { s[j] *= 0.125f; m = fmaxf(m, s[j]); }
    float sum = 0.f;
#pragma unroll
    for (int j = 0; j < 64; j++) { s[j] = expf(s[j] - m); sum += s[j]; }
    float inv = 1.f / sum;
    __syncthreads();
    for (int i = 0; i < 64; i++) KV[i][t] = vbase[i*D_ + t];
    __syncthreads();
    float* outrow = g_ctx + (b*K_ + t)*D_ + h*HD_;
    for (int d = 0; d < 64; d++) {
        float acc = 0.f;
#pragma unroll
        for (int j = 0; j < 64; j++) acc += s[j] * KV[j][d];
        outrow[d] = acc * inv;
    }
}

// ---------------- 8. scatter-broadcast output ----------------
__global__ void scatter_kernel(float* __restrict__ out) {
    int bg = blockIdx.x;
    int b = bg >> 9, g = bg & 511;
    int k = g_selmap[bg];
    int d4 = threadIdx.x * 4;
    float4 v = make_float4(0.f, 0.f, 0.f, 0.f);
    if (k >= 0) v = *(const float4*)(g_outg + ((b << 6) + k)*D_ + d4);
    float* dst = out + (b*S_ + g*GS_)*D_ + d4;
#pragma unroll
    for (int r = 0; r < GS_; r++) *(float4*)(dst + r*D_) = v;
}

// ---------------- launch ----------------
extern "C" void kernel_launch(void* const* d_in, const int* in_sizes, int n_in,
                              void* d_out, int out_size) {
    const float* hs  = (const float*)d_in[0];
    const float* Wq  = (const float*)d_in[1];
    const float* Wk  = (const float*)d_in[2];
    const float* Wv  = (const float*)d_in[3];
    const float* Wo  = (const float*)d_in[4];
    const float* Ws1 = (const float*)d_in[5];
    const float* bs1 = (const float*)d_in[6];
    const float* Ws2 = (const float*)d_in[7];
    const float* bs2 = (const float*)d_in[8];
    float* out = (float*)d_out;

    float *p_groups, *p_h, *p_q, *p_k, *p_v, *p_ctx, *p_outg;
    cudaGetSymbolAddress((void**)&p_groups, g_groups);
    cudaGetSymbolAddress((void**)&p_h,      g_h);
    cudaGetSymbolAddress((void**)&p_q,      g_q);
    cudaGetSymbolAddress((void**)&p_k,      g_k);
    cudaGetSymbolAddress((void**)&p_v,      g_v);
    cudaGetSymbolAddress((void**)&p_ctx,    g_ctx);
    cudaGetSymbolAddress((void**)&p_outg,   g_outg);

    pool_kernel<<<BG_, 256>>>(hs);
    // scorer hidden: [4096,1024] @ [1024,256]
    gemm_tf32_3x<false><<<dim3(F_/64, BG_/64, 1), 128>>>(p_groups, Ws1, Ws1, Ws1,
                                                         p_h, p_h, p_h, BG_, F_, D_);
    score_reduce<<<BG_/8, 256>>>(bs1, Ws2, bs2);
    topk_bitonic<<<B_, 512>>>();
    // QKV fused, gather fused via rowmap: [512,1024] @ [1024,1024] x3
    gemm_tf32_3x<true><<<dim3(D_/64, BK_/64, 3), 128>>>(p_groups, Wq, Wk, Wv,
                                                        p_q, p_k, p_v, BK_, D_, D_);
    attn_kernel<<<B_*H_, 64>>>();
    // Wo: [512,1024] @ [1024,1024]
    gemm_tf32_3x<false><<<dim3(D_/64, BK_/64, 1), 128>>>(p_ctx, Wo, Wo, Wo,
                                                         p_outg, p_outg, p_outg, BK_, D_, D_);
    scatter_kernel<<<BG_, 256>>>(out);
}